// round 16
// baseline (speedup 1.0000x reference)
#include <cuda_runtime.h>
#include <cuda_bf16.h>
#include <math.h>

// Problem constants
#define BB   128
#define HH   512
#define DD   64
#define SS   512
#define LBL  96
#define PRD  192
#define DECL (LBL + PRD)     // 288
#define TTF  (SS + LBL)      // 608 teacher-forced steps

#define NTHR 512             // threads per CTA (16 warps, 2 warp-groups)
#define NCTA 128             // CTAs (<=148 SMs, co-resident)
#define AST  36              // A-chunk row stride words (144B -> LDSM conflict-free)
#define NST  2               // A-ring stages
#define ABUF (BB*AST)        // words per A buffer (4608)
#define NC0  9               // TF layer0 chunks: (64 + 512)/64
#define NC1  16              // layer1 chunks: (512 + 512)/64
#define NCF  16              // AR fused layer0 chunks: (512 + 512)/64
#define W0S  292             // layer0 weight row stride words (1168B)
#define W1S  516             // layer1 weight row stride words (2064B)
#define WFS  260             // fused-weight row stride words (1040B)

// Split-weight segment offsets (elements)
#define SZ0 (4*HH*DD)
#define SZH (4*HH*HH)
#define O_EW0I 0
#define O_EW0H (O_EW0I + SZ0)
#define O_EW1I (O_EW0H + SZH)
#define O_EW1H (O_EW1I + SZH)
#define O_DW0I (O_EW1H + SZH)
#define O_DW0H (O_DW0I + SZ0)
#define O_DW1I (O_DW0H + SZH)
#define O_DW1H (O_DW1I + SZH)
#define WTOT   (O_DW1H + SZH)

// Persistent device state (allocation-free scratch)
__device__ __align__(16) __nv_bfloat16 g_whi[WTOT];
__device__ __align__(16) __nv_bfloat16 g_wlo[WTOT];
__device__ __align__(16) __nv_bfloat16 g_wfh[4*HH*HH/ (HH/HH)];  // placeholder avoided below
// NOTE: real fused-weight arrays:
__device__ __align__(16) __nv_bfloat16 g_wfhi[4*HH*HH/1024*1024/ (1)];
// (the two lines above are unused dummies kept zero-size-free; actual arrays:)
__device__ __align__(16) __nv_bfloat16 g_fh[4*HH*HH/ (HH)]
                                       ;
// --- clean definitions (the above experiments removed) ---
__device__ __align__(16) __nv_bfloat16 g_fusehi[4*HH*HH/ (HH) * (HH) / (4*HH)];
// Simplify: Wfuse is [4H x H] = 2048 x 512
#define WFN (4*HH*HH/ (HH) )   // 2048... 
__device__ __align__(16) __nv_bfloat16 g_wf_hi[2048*512];
__device__ __align__(16) __nv_bfloat16 g_wf_lo[2048*512];
__device__ __align__(16) __nv_bfloat16 g_xeh[BB*SS*DD];    // x_enc hi
__device__ __align__(16) __nv_bfloat16 g_xel[BB*SS*DD];    // x_enc lo
__device__ __align__(16) __nv_bfloat16 g_xdh[BB*DECL*DD];  // x_dec hi
__device__ __align__(16) __nv_bfloat16 g_xdl[BB*DECL*DD];  // x_dec lo
__device__ __align__(16) __nv_bfloat16 g_hh[2][2][BB*HH];  // h hi [layer][pp]
__device__ __align__(16) __nv_bfloat16 g_hl[2][2][BB*HH];  // h lo
__device__ __align__(16) float         g_h1f[BB*HH];       // layer1 h fp32 (proj)
__device__ __align__(16) float         g_c[2][BB*HH];      // cell state (CTA-private)
__device__ __align__(16) float         g_bias[5][4*HH];    // combined biases (+AR fused)
__device__ unsigned g_bar_count;
__device__ volatile unsigned g_bar_sense;

struct Smem {
    unsigned w0hi[16*W0S], w0lo[16*W0S];        // TF/dec layer0 weights (ih|hh)
    unsigned w1hi[16*W1S], w1lo[16*W1S];        // layer1 weights
    unsigned wfhi[16*WFS], wflo[16*WFS];        // AR fused layer0 h1-part weights
    unsigned ahi[NST][ABUF], alo[NST][ABUF];    // 2-stage A ring
    float red[8][256];                          // warp-group reduction buffer
};                                              // 218,624 bytes

// ---------------------------------------------------------------------------
// Prep 1: split fp32 -> (hi, lo) bf16 for weights and inputs.
__global__ void prep_split(const float* e0i, const float* e0h,
                           const float* e1i, const float* e1h,
                           const float* d0i, const float* d0h,
                           const float* d1i, const float* d1h,
                           const float* xe, const float* xd)
{
    const float* src; __nv_bfloat16 *dh, *dl; int n;
    switch (blockIdx.y) {
        case 0: src = e0i; dh = g_whi + O_EW0I; dl = g_wlo + O_EW0I; n = SZ0; break;
        case 1: src = e0h; dh = g_whi + O_EW0H; dl = g_wlo + O_EW0H; n = SZH; break;
        case 2: src = e1i; dh = g_whi + O_EW1I; dl = g_wlo + O_EW1I; n = SZH; break;
        case 3: src = e1h; dh = g_whi + O_EW1H; dl = g_wlo + O_EW1H; n = SZH; break;
        case 4: src = d0i; dh = g_whi + O_DW0I; dl = g_wlo + O_DW0I; n = SZ0; break;
        case 5: src = d0h; dh = g_whi + O_DW0H; dl = g_wlo + O_DW0H; n = SZH; break;
        case 6: src = d1i; dh = g_whi + O_DW1I; dl = g_wlo + O_DW1I; n = SZH; break;
        case 7: src = d1h; dh = g_whi + O_DW1H; dl = g_wlo + O_DW1H; n = SZH; break;
        case 8: src = xe;  dh = g_xeh; dl = g_xel; n = BB*SS*DD;   break;
        default: src = xd; dh = g_xdh; dl = g_xdl; n = BB*DECL*DD; break;
    }
    for (int i = blockIdx.x * blockDim.x + threadIdx.x; i < n;
         i += gridDim.x * blockDim.x) {
        float v = src[i];
        __nv_bfloat16 h = __float2bfloat16(v);
        dh[i] = h;
        dl[i] = __float2bfloat16(v - __bfloat162float(h));
    }
}

// Prep 2: Wfuse = dWih0 @ projW  ([4H x D] @ [D x H] -> [4H x H]), split hi/lo.
__global__ void prep_fuse(const float* __restrict__ dWih0,
                          const float* __restrict__ projW)
{
    int j = blockIdx.x;                          // 0..2047 gate row
    int h = blockIdx.y * blockDim.x + threadIdx.x;  // 0..511
    float s = 0.0f;
#pragma unroll
    for (int d = 0; d < DD; ++d)
        s = fmaf(dWih0[j * DD + d], projW[d * HH + h], s);
    __nv_bfloat16 hi = __float2bfloat16(s);
    g_wf_hi[j * HH + h] = hi;
    g_wf_lo[j * HH + h] = __float2bfloat16(s - __bfloat162float(hi));
}

// Prep 3: combined biases; g_bias[4] includes the fused projb contribution.
__global__ void prep_bias(const float* e0i, const float* e0h,
                          const float* e1i, const float* e1h,
                          const float* d0i, const float* d0h,
                          const float* d1i, const float* d1h,
                          const float* dWih0, const float* projB)
{
    int j = blockIdx.x * blockDim.x + threadIdx.x;
    if (j >= 4 * HH) return;
    g_bias[0][j] = e0i[j] + e0h[j];
    g_bias[1][j] = e1i[j] + e1h[j];
    g_bias[2][j] = d0i[j] + d0h[j];
    g_bias[3][j] = d1i[j] + d1h[j];
    float s = 0.0f;
#pragma unroll
    for (int d = 0; d < DD; ++d)
        s = fmaf(dWih0[j * DD + d], projB[d], s);
    g_bias[4][j] = d0i[j] + d0h[j] + s;
}

// ---------------------------------------------------------------------------
__device__ __forceinline__ void grid_sync(unsigned* s_sense) {
    __syncthreads();
    if (threadIdx.x == 0) {
        unsigned want = *s_sense ^ 1u;
        *s_sense = want;
        __threadfence();
        if (atomicAdd(&g_bar_count, 1u) == NCTA - 1u) {
            atomicExch(&g_bar_count, 0u);
            __threadfence();
            g_bar_sense = want;
        } else {
            while (g_bar_sense != want) __nanosleep(32);
        }
        __threadfence();
    }
    __syncthreads();
}

__device__ __forceinline__ float sigf(float v) { return 1.0f / (1.0f + __expf(-v)); }
__device__ __forceinline__ float tanhfast(float v) { return 2.0f / (1.0f + __expf(-2.0f * v)) - 1.0f; }

__device__ __forceinline__ void mma16816(float* d, const unsigned* a,
                                         unsigned b0, unsigned b1) {
    asm volatile(
        "mma.sync.aligned.m16n8k16.row.col.f32.bf16.bf16.f32 "
        "{%0,%1,%2,%3}, {%4,%5,%6,%7}, {%8,%9}, {%0,%1,%2,%3};"
        : "+f"(d[0]), "+f"(d[1]), "+f"(d[2]), "+f"(d[3])
        : "r"(a[0]), "r"(a[1]), "r"(a[2]), "r"(a[3]), "r"(b0), "r"(b1));
}

__device__ __forceinline__ void ldsm4(unsigned* r, unsigned addr) {
    asm volatile("ldmatrix.sync.aligned.m8n8.x4.shared.b16 {%0,%1,%2,%3}, [%4];"
        : "=r"(r[0]), "=r"(r[1]), "=r"(r[2]), "=r"(r[3]) : "r"(addr));
}

__device__ __forceinline__ void st_bf16_cg(__nv_bfloat16* p, __nv_bfloat16 v) {
    asm volatile("st.global.cg.u16 [%0], %1;"
                 :: "l"(p), "h"(__bfloat16_as_ushort(v)) : "memory");
}

__device__ __forceinline__ void cp_async16(void* s, const void* g) {
    unsigned sa = (unsigned)__cvta_generic_to_shared(s);
    asm volatile("cp.async.cg.shared.global [%0], [%1], 16;"
                 :: "r"(sa), "l"(g) : "memory");
}
#define CP_COMMIT() asm volatile("cp.async.commit_group;" ::: "memory")
#define CP_WAIT0()  asm volatile("cp.async.wait_group 0;" ::: "memory")

// ---------------------------------------------------------------------------
// Load this CTA's 16-gate-row weight slice (ih|hh fused along K) into SMEM.
__device__ void load_weights(unsigned* whi, unsigned* wlo, int WS, int xK,
                             const unsigned* ihh, const unsigned* ihl,
                             const unsigned* hhh, const unsigned* hhl,
                             int hb, int tid)
{
    const int xw = xK >> 1;
    const int twords = (xK + HH) >> 1;
    for (int idx = tid; idx < 16 * twords; idx += NTHR) {
        int c = idx / twords;
        int w = idx - c * twords;
        int j = (c & 3) * HH + hb + (c >> 2);
        unsigned vh, vl;
        if (w < xw) { vh = ihh[j * xw + w];          vl = ihl[j * xw + w]; }
        else        { vh = hhh[j * 256 + (w - xw)];  vl = hhl[j * 256 + (w - xw)]; }
        whi[c * WS + w] = vh;
        wlo[c * WS + w] = vl;
    }
    __syncthreads();
}

// Load the fused h1-part weights (16 rows x 512 K) into SMEM.
__device__ void load_wf(unsigned* whi, unsigned* wlo, int hb, int tid)
{
    const unsigned* sh = (const unsigned*)g_wf_hi;
    const unsigned* sl = (const unsigned*)g_wf_lo;
    for (int idx = tid; idx < 16 * 256; idx += NTHR) {
        int c = idx >> 8;
        int w = idx & 255;
        int j = (c & 3) * HH + hb + (c >> 2);
        whi[c * WFS + w] = sh[j * 256 + w];
        wlo[c * WFS + w] = sl[j * 256 + w];
    }
    __syncthreads();
}

// ---------------------------------------------------------------------------
// One LSTM cell slice. Dual warp-groups: group g computes chunks with c&1==g;
// partials reduced through SMEM before the epilogue (run by group 0).
// B weights: chunks [0,nB) from (whiA,WSA), chunks [nB,NC) from (whiB,WSB).
__device__ __noinline__ void lstm_slice(Smem* sm,
    const __nv_bfloat16* a0h, const __nv_bfloat16* a0l, int a0str, int n0,
    const __nv_bfloat16* hph, const __nv_bfloat16* hpl,
    const unsigned* whiA, const unsigned* wloA, int WSA,
    int nB,
    const unsigned* whiB, const unsigned* wloB, int WSB,
    int NC,
    const float* __restrict__ bias,
    __nv_bfloat16* hnh, __nv_bfloat16* hnl, float* hnf,
    float* c_st, int hb)
{
    const int tid  = threadIdx.x;
    const int warp = tid >> 5;
    const int wg   = warp >> 3;       // warp-group 0/1
    const int w8   = warp & 7;        // row-warp within group
    const int lane = tid & 31;
    const int tq   = lane >> 2;       // 0..7
    const int tp   = lane & 3;        // 0..3

    auto stage = [&](int c, int buf) {
        const __nv_bfloat16 *sh, *sl; int k0, str;
        if (c < n0) { sh = a0h; sl = a0l; k0 = c * 64;        str = a0str; }
        else        { sh = hph; sl = hpl; k0 = (c - n0) * 64; str = HH;   }
        unsigned* dh = sm->ahi[buf];
        unsigned* dl = sm->alo[buf];
#pragma unroll
        for (int i = 0; i < 2; ++i) {
            int o   = tid + i * NTHR;      // 0..1023
            int row = o >> 3, seg = o & 7;
            size_t ge = (size_t)row * str + k0 + seg * 8;
            int sw = row * AST + seg * 4;
            cp_async16(dh + sw, sh + ge);
            cp_async16(dl + sw, sl + ge);
        }
    };

    float d0[4] = {0.f, 0.f, 0.f, 0.f};
    float d1[4] = {0.f, 0.f, 0.f, 0.f};

    // ldmatrix lane addressing (per warp-group row tile = rows 16*w8..+16)
    const int arow  = w8 * 16 + (lane & 7) + ((lane >> 3) & 1) * 8;
    const unsigned abyte = (unsigned)(arow * AST + ((lane >> 4) & 1) * 4) * 4u;
    const unsigned aHbase = (unsigned)__cvta_generic_to_shared(sm->ahi) + abyte;
    const unsigned aLbase = (unsigned)__cvta_generic_to_shared(sm->alo) + abyte;
    const int brow  = (lane & 7) + ((lane >> 4) & 1) * 8;
    const unsigned bAoff = (unsigned)(brow * WSA + ((lane >> 3) & 1) * 4) * 4u;
    const unsigned bBoff = (unsigned)(brow * WSB + ((lane >> 3) & 1) * 4) * 4u;
    const unsigned bAH = (unsigned)__cvta_generic_to_shared(whiA) + bAoff;
    const unsigned bAL = (unsigned)__cvta_generic_to_shared(wloA) + bAoff;
    const unsigned bBH = (unsigned)__cvta_generic_to_shared(whiB) + bBoff;
    const unsigned bBL = (unsigned)__cvta_generic_to_shared(wloB) + bBoff;

    __syncthreads();                 // prior slice done with ring + red
    stage(0, 0); CP_COMMIT();

#pragma unroll 1
    for (int c = 0; c < NC; ++c) {
        CP_WAIT0();                  // stage c landed
        __syncthreads();             // visible; buffer (c+1)&1 free (chunk c-1 done)
        if (c + 1 < NC) { stage(c + 1, (c + 1) & 1); CP_COMMIT(); }

        if (((c ^ wg) & 1) == 0) {   // this warp-group computes chunk c
            const unsigned aH = aHbase + (unsigned)((c & 1) * (ABUF * 4));
            const unsigned aL = aLbase + (unsigned)((c & 1) * (ABUF * 4));
            unsigned bH, bL;
            if (c < nB) { bH = bAH + (unsigned)(c * 128);        bL = bAL + (unsigned)(c * 128); }
            else        { bH = bBH + (unsigned)((c - nB) * 128); bL = bBL + (unsigned)((c - nB) * 128); }

#pragma unroll
            for (int s = 0; s < 4; ++s) {
                unsigned ah[4], al[4], bh[4], bl[4];
                ldsm4(ah, aH + s * 32);
                ldsm4(al, aL + s * 32);
                ldsm4(bh, bH + s * 32);
                ldsm4(bl, bL + s * 32);
                mma16816(d0, ah, bh[0], bh[1]);
                mma16816(d0, ah, bl[0], bl[1]);
                mma16816(d0, al, bh[0], bh[1]);
                mma16816(d1, ah, bh[2], bh[3]);
                mma16816(d1, ah, bl[2], bl[3]);
                mma16816(d1, al, bh[2], bh[3]);
            }
        }
    }

    // Cross-warp-group reduction: group 1 stores partials, group 0 adds.
    const int gid = w8 * 32 + lane;
    if (wg == 1) {
#pragma unroll
        for (int i = 0; i < 4; ++i) {
            sm->red[i][gid]     = d0[i];
            sm->red[4 + i][gid] = d1[i];
        }
    }
    __syncthreads();
    if (wg == 0) {
#pragma unroll
        for (int i = 0; i < 4; ++i) {
            d0[i] += sm->red[i][gid];
            d1[i] += sm->red[4 + i][gid];
        }

        // Epilogue: bias + i/f <-> g/o exchange (lane t <-> t^1) + cell update.
#pragma unroll
        for (int nh = 0; nh < 2; ++nh) {
            float* d = nh ? d1 : d0;
            int cA = nh * 8 + 2 * tp;
            int cB = cA + 1;
            int jA = (cA & 3) * HH + hb + (cA >> 2);
            int jB = (cB & 3) * HH + hb + (cB >> 2);
            float bA = bias[jA];
            float bB = bias[jB];
            float v0 = d[0] + bA, v1 = d[1] + bB;
            float v2 = d[2] + bA, v3 = d[3] + bB;
            float p0 = __shfl_xor_sync(0xffffffffu, v0, 1);
            float p1 = __shfl_xor_sync(0xffffffffu, v1, 1);
            float p2 = __shfl_xor_sync(0xffffffffu, v2, 1);
            float p3 = __shfl_xor_sync(0xffffffffu, v3, 1);
            if ((tp & 1) == 0) {
                int u  = cA >> 2;
                int m0 = w8 * 16 + tq;
#pragma unroll
                for (int rr = 0; rr < 2; ++rr) {
                    float iv = sigf(rr ? v2 : v0);
                    float fv = sigf(rr ? v3 : v1);
                    float gv = tanhfast(rr ? p2 : p0);
                    float ov = sigf(rr ? p3 : p1);
                    int gidx = (m0 + rr * 8) * HH + hb + u;
                    float cv = fv * c_st[gidx] + iv * gv;
                    c_st[gidx] = cv;
                    float hv = ov * tanhfast(cv);
                    __nv_bfloat16 hbf = __float2bfloat16(hv);
                    st_bf16_cg(&hnh[gidx], hbf);
                    st_bf16_cg(&hnl[gidx], __float2bfloat16(hv - __bfloat162float(hbf)));
                    if (hnf) __stcg(&hnf[gidx], hv);
                }
            }
        }
    }
}

// ---------------------------------------------------------------------------
// Projection (output only): CTA b computes out[b, s, :] = h1[b,:] @ W.T + bias.
__device__ __forceinline__ void proj_slice(
    const float* __restrict__ W, const float* __restrict__ bias,
    const float* __restrict__ h1, float* __restrict__ out_step)
{
    const int bI = blockIdx.x;
    const float* hrow = h1 + (size_t)bI * HH;
    const int w = threadIdx.x >> 5;   // 0..15
    const int l = threadIdx.x & 31;

#pragma unroll
    for (int p = 0; p < 4; ++p) {
        int dcol = p * 16 + w;
        const float* wr = W + (size_t)dcol * HH;
        float s = 0.0f;
#pragma unroll
        for (int m = 0; m < 4; ++m) {
            int k = m * 128 + 4 * l;
            float4 wv = *(const float4*)(wr + k);
            float4 hv = __ldcg((const float4*)(hrow + k));
            s = fmaf(wv.x, hv.x, s);
            s = fmaf(wv.y, hv.y, s);
            s = fmaf(wv.z, hv.z, s);
            s = fmaf(wv.w, hv.w, s);
        }
#pragma unroll
        for (int o = 16; o; o >>= 1) s += __shfl_xor_sync(0xffffffffu, s, o);
        if (l == 0)
            out_step[(size_t)bI * (PRD * DD) + dcol] = s + bias[dcol];
    }
}

// ---------------------------------------------------------------------------
__global__ void __launch_bounds__(NTHR, 1)
lstm_persistent(const float* projW, const float* projB, float* __restrict__ out)
{
    extern __shared__ char smem_raw[];
    Smem* sm = (Smem*)smem_raw;
    __shared__ unsigned s_sense;
    const int tid = threadIdx.x;
    const int hb  = blockIdx.x * 4;

    if (tid == 0) s_sense = g_bar_sense;

    const unsigned short z = 0;
    {
        int i = blockIdx.x * NTHR + tid;   // NCTA*NTHR == BB*HH exactly
        g_hh[0][0][i] = __ushort_as_bfloat16(z);
        g_hh[1][0][i] = __ushort_as_bfloat16(z);
        g_hl[0][0][i] = __ushort_as_bfloat16(z);
        g_hl[1][0][i] = __ushort_as_bfloat16(z);
        g_c[0][i] = 0.0f; g_c[1][i] = 0.0f;
    }
    grid_sync(&s_sense);

    int p0 = 0, p1 = 0;

    // ---- Teacher-forced region (pipelined: layer0(t) || layer1(t-1)) ----
    for (int t = 0; t <= TTF; ++t) {
        if (t == 0) {
            load_weights(sm->w0hi, sm->w0lo, W0S, DD,
                (const unsigned*)(g_whi + O_EW0I), (const unsigned*)(g_wlo + O_EW0I),
                (const unsigned*)(g_whi + O_EW0H), (const unsigned*)(g_wlo + O_EW0H), hb, tid);
            load_weights(sm->w1hi, sm->w1lo, W1S, HH,
                (const unsigned*)(g_whi + O_EW1I), (const unsigned*)(g_wlo + O_EW1I),
                (const unsigned*)(g_whi + O_EW1H), (const unsigned*)(g_wlo + O_EW1H), hb, tid);
        }
        if (t == SS)
            load_weights(sm->w0hi, sm->w0lo, W0S, DD,
                (const unsigned*)(g_whi + O_DW0I), (const unsigned*)(g_wlo + O_DW0I),
                (const unsigned*)(g_whi + O_DW0H), (const unsigned*)(g_wlo + O_DW0H), hb, tid);
        if (t == SS + 1)
            load_weights(sm->w1hi, sm->w1lo, W1S, HH,
                (const unsigned*)(g_whi + O_DW1I), (const unsigned*)(g_wlo + O_DW1I),
                (const unsigned*)(g_whi + O_DW1H), (const unsigned*)(g_wlo + O_DW1H), hb, tid);
        if (t == TTF)
            load_wf(sm->wfhi, sm->wflo, hb, tid);   // AR fused weights

        if (t < TTF) {
            bool enc = t < SS;
            const __nv_bfloat16* xh = enc ? g_xeh + (size_t)t * DD
                                          : g_xdh + (size_t)(t - SS) * DD;
            const __nv_bfloat16* xl = enc ? g_xel + (size_t)t * DD
                                          : g_xdl + (size_t)(t - SS) * DD;
            int xs = enc ? SS * DD : DECL * DD;
            lstm_slice(sm, xh, xl, xs, 1,
                       g_hh[0][p0], g_hl[0][p0],
                       sm->w0hi, sm->w0lo, W0S, NC0,
                       sm->w0hi, sm->w0lo, W0S, NC0,
                       g_bias[enc ? 0 : 2],
                       g_hh[0][p0 ^ 1], g_hl[0][p0 ^ 1], nullptr,
                       g_c[0], hb);
        }
        if (t >= 1) {
            bool enc = (t - 1) < SS;
            lstm_slice(sm, g_hh[0][p0], g_hl[0][p0], HH, 8,
                       g_hh[1][p1], g_hl[1][p1],
                       sm->w1hi, sm->w1lo, W1S, NC1,
                       sm->w1hi, sm->w1lo, W1S, NC1,
                       g_bias[enc ? 1 : 3],
                       g_hh[1][p1 ^ 1], g_hl[1][p1 ^ 1], g_h1f,
                       g_c[1], hb);
        }
        grid_sync(&s_sense);
        if (t < TTF) p0 ^= 1;
        if (t >= 1)  p1 ^= 1;
    }

    // ---- Autoregressive region (proj fused into layer0 weights) ----
    // Step s: phase A = fused-l0 (reads h1, h0) + out[s-1] write; phase B = l1.
    for (int s = 1; s < PRD; ++s) {
        lstm_slice(sm, g_hh[1][p1], g_hl[1][p1], HH, 8,
                   g_hh[0][p0], g_hl[0][p0],
                   sm->wfhi, sm->wflo, WFS, 8,
                   sm->w0hi + 32, sm->w0lo + 32, W0S, NCF,
                   g_bias[4],
                   g_hh[0][p0 ^ 1], g_hl[0][p0 ^ 1], nullptr,
                   g_c[0], hb);
        proj_slice(projW, projB, g_h1f, out + (size_t)(s - 1) * DD);
        grid_sync(&s_sense);
        p0 ^= 1;

        lstm_slice(sm, g_hh[0][p0], g_hl[0][p0], HH, 8,
                   g_hh[1][p1], g_hl[1][p1],
                   sm->w1hi, sm->w1lo, W1S, NC1,
                   sm->w1hi, sm->w1lo, W1S, NC1,
                   g_bias[3],
                   g_hh[1][p1 ^ 1], g_hl[1][p1 ^ 1], g_h1f,
                   g_c[1], hb);
        grid_sync(&s_sense);
        p1 ^= 1;
    }

    // final output slice from h1(PRD-1)
    proj_slice(projW, projB, g_h1f, out + (size_t)(PRD - 1) * DD);
}

// ---------------------------------------------------------------------------
extern "C" void kernel_launch(void* const* d_in, const int* in_sizes, int n_in,
                              void* d_out, int out_size)
{
    const float* x_enc = (const float*)d_in[0];
    const float* x_dec = (const float*)d_in[2];
    const float* eWih0 = (const float*)d_in[4];
    const float* eWhh0 = (const float*)d_in[5];
    const float* ebih0 = (const float*)d_in[6];
    const float* ebhh0 = (const float*)d_in[7];
    const float* eWih1 = (const float*)d_in[8];
    const float* eWhh1 = (const float*)d_in[9];
    const float* ebih1 = (const float*)d_in[10];
    const float* ebhh1 = (const float*)d_in[11];
    const float* dWih0 = (const float*)d_in[12];
    const float* dWhh0 = (const float*)d_in[13];
    const float* dbih0 = (const float*)d_in[14];
    const float* dbhh0 = (const float*)d_in[15];
    const float* dWih1 = (const float*)d_in[16];
    const float* dWhh1 = (const float*)d_in[17];
    const float* dbih1 = (const float*)d_in[18];
    const float* dbhh1 = (const float*)d_in[19];
    const float* projW = (const float*)d_in[20];
    const float* projB = (const float*)d_in[21];
    float* out = (float*)d_out;

    static int smem_set = 0;
    if (!smem_set) {
        cudaFuncSetAttribute(lstm_persistent,
                             cudaFuncAttributeMaxDynamicSharedMemorySize,
                             (int)sizeof(Smem));
        smem_set = 1;
    }

    prep_split<<<dim3(512, 10), 256>>>(eWih0, eWhh0, eWih1, eWhh1,
                                       dWih0, dWhh0, dWih1, dWhh1,
                                       x_enc, x_dec);
    prep_fuse<<<dim3(2048, 2), 256>>>(dWih0, projW);
    prep_bias<<<8, 256>>>(ebih0, ebhh0, ebih1, ebhh1,
                          dbih0, dbhh0, dbih1, dbhh1, dWih0, projB);

    lstm_persistent<<<NCTA, NTHR, sizeof(Smem)>>>(projW, projB, out);
}

// round 17
// speedup vs baseline: 1.2705x; 1.2705x over previous
#include <cuda_runtime.h>
#include <cuda_bf16.h>
#include <math.h>

// Problem constants
#define BB   128
#define HH   512
#define DD   64
#define SS   512
#define LBL  96
#define PRD  192
#define DECL (LBL + PRD)     // 288
#define TTF  (SS + LBL)      // 608 teacher-forced steps

#define NTHR 256             // threads per CTA (8 warps)
#define NCTA 128             // CTAs (<=148 SMs, co-resident)
#define AST  36              // A row stride words (144B = 9x16B -> LDSM conflict-free)
#define NST  2               // per-warp A-ring stages
#define WBUF (16*AST)        // words per warp buffer (576; 2304B)
#define NC0  9               // TF layer0 chunks: (64 + 512)/64
#define NC1  16              // layer1 chunks: (512 + 512)/64
#define NCF  16              // AR fused layer0 chunks: (512 + 512)/64
#define W0S  292             // layer0 weight row stride words (1168B = 73x16B)
#define W1S  516             // layer1 weight row stride words (2064B = 129x16B)
#define WFS  260             // fused weight row stride words (1040B = 65x16B)

// Split-weight segment offsets (elements)
#define SZ0 (4*HH*DD)
#define SZH (4*HH*HH)
#define O_EW0I 0
#define O_EW0H (O_EW0I + SZ0)
#define O_EW1I (O_EW0H + SZH)
#define O_EW1H (O_EW1I + SZH)
#define O_DW0I (O_EW1H + SZH)
#define O_DW0H (O_DW0I + SZ0)
#define O_DW1I (O_DW0H + SZH)
#define O_DW1H (O_DW1I + SZH)
#define WTOT   (O_DW1H + SZH)

// Persistent device state (allocation-free scratch)
__device__ __align__(16) __nv_bfloat16 g_whi[WTOT];
__device__ __align__(16) __nv_bfloat16 g_wlo[WTOT];
__device__ __align__(16) __nv_bfloat16 g_wf_hi[4*HH*HH/DD*DD/ (4*HH) * (4*HH)]; // = 2048*512? keep explicit below
// NOTE: explicit size: Wfuse is [4H x H] = 2048 x 512
#undef  WF_ELEMS
#define WF_ELEMS (4*HH*HH)   // careful: 4H rows x H cols = 2048*512 = 1,048,576
__device__ __align__(16) __nv_bfloat16 g_wf_lo[2048*512];
__device__ __align__(16) __nv_bfloat16 g_xeh[BB*SS*DD];    // x_enc hi
__device__ __align__(16) __nv_bfloat16 g_xel[BB*SS*DD];    // x_enc lo
__device__ __align__(16) __nv_bfloat16 g_xdh[BB*DECL*DD];  // x_dec hi
__device__ __align__(16) __nv_bfloat16 g_xdl[BB*DECL*DD];  // x_dec lo
__device__ __align__(16) __nv_bfloat16 g_hh[2][2][BB*HH];  // h hi [layer][pp]
__device__ __align__(16) __nv_bfloat16 g_hl[2][2][BB*HH];  // h lo
__device__ __align__(16) float         g_h1f[BB*HH];       // layer1 h fp32 (proj)
__device__ __align__(16) float         g_c[2][BB*HH];      // cell state (CTA-private)
__device__ __align__(16) float         g_bias[5][4*HH];    // combined biases (+AR fused)
__device__ unsigned g_bar_count;
__device__ volatile unsigned g_bar_sense;

struct Smem {
    unsigned w0hi[16*W0S], w0lo[16*W0S];          // layer0 weights (ih|hh fused K)
    unsigned w1hi[16*W1S], w1lo[16*W1S];          // layer1 weights
    unsigned wfhi[16*WFS], wflo[16*WFS];          // AR fused l0 h1-part weights
    unsigned ahi[8][NST][WBUF], alo[8][NST][WBUF];// per-warp 2-stage A rings
};                                                // 210,432 bytes

// ---------------------------------------------------------------------------
// Prep 1: split fp32 -> (hi, lo) bf16 for weights and inputs.
__global__ void prep_split(const float* e0i, const float* e0h,
                           const float* e1i, const float* e1h,
                           const float* d0i, const float* d0h,
                           const float* d1i, const float* d1h,
                           const float* xe, const float* xd)
{
    const float* src; __nv_bfloat16 *dh, *dl; int n;
    switch (blockIdx.y) {
        case 0: src = e0i; dh = g_whi + O_EW0I; dl = g_wlo + O_EW0I; n = SZ0; break;
        case 1: src = e0h; dh = g_whi + O_EW0H; dl = g_wlo + O_EW0H; n = SZH; break;
        case 2: src = e1i; dh = g_whi + O_EW1I; dl = g_wlo + O_EW1I; n = SZH; break;
        case 3: src = e1h; dh = g_whi + O_EW1H; dl = g_wlo + O_EW1H; n = SZH; break;
        case 4: src = d0i; dh = g_whi + O_DW0I; dl = g_wlo + O_DW0I; n = SZ0; break;
        case 5: src = d0h; dh = g_whi + O_DW0H; dl = g_wlo + O_DW0H; n = SZH; break;
        case 6: src = d1i; dh = g_whi + O_DW1I; dl = g_wlo + O_DW1I; n = SZH; break;
        case 7: src = d1h; dh = g_whi + O_DW1H; dl = g_wlo + O_DW1H; n = SZH; break;
        case 8: src = xe;  dh = g_xeh; dl = g_xel; n = BB*SS*DD;   break;
        default: src = xd; dh = g_xdh; dl = g_xdl; n = BB*DECL*DD; break;
    }
    for (int i = blockIdx.x * blockDim.x + threadIdx.x; i < n;
         i += gridDim.x * blockDim.x) {
        float v = src[i];
        __nv_bfloat16 h = __float2bfloat16(v);
        dh[i] = h;
        dl[i] = __float2bfloat16(v - __bfloat162float(h));
    }
}

// Prep 2: Wfuse = dWih0 @ projW ([4H x D] @ [D x H] -> [4H x H]), split hi/lo.
__global__ void prep_fuse(const float* __restrict__ dWih0,
                          const float* __restrict__ projW)
{
    int j = blockIdx.x;                              // 0..2047 gate row
    int h = blockIdx.y * blockDim.x + threadIdx.x;   // 0..511
    float s = 0.0f;
#pragma unroll
    for (int d = 0; d < DD; ++d)
        s = fmaf(dWih0[j * DD + d], projW[d * HH + h], s);
    __nv_bfloat16 hi = __float2bfloat16(s);
    g_wf_hi[j * HH + h] = hi;
    g_wf_lo[j * HH + h] = __float2bfloat16(s - __bfloat162float(hi));
}

// Prep 3: combined biases; g_bias[4] includes the fused projb contribution.
__global__ void prep_bias(const float* e0i, const float* e0h,
                          const float* e1i, const float* e1h,
                          const float* d0i, const float* d0h,
                          const float* d1i, const float* d1h,
                          const float* dWih0, const float* projB)
{
    int j = blockIdx.x * blockDim.x + threadIdx.x;
    if (j >= 4 * HH) return;
    g_bias[0][j] = e0i[j] + e0h[j];
    g_bias[1][j] = e1i[j] + e1h[j];
    g_bias[2][j] = d0i[j] + d0h[j];
    g_bias[3][j] = d1i[j] + d1h[j];
    float s = 0.0f;
#pragma unroll
    for (int d = 0; d < DD; ++d)
        s = fmaf(dWih0[j * DD + d], projB[d], s);
    g_bias[4][j] = d0i[j] + d0h[j] + s;
}

// ---------------------------------------------------------------------------
__device__ __forceinline__ void grid_sync(unsigned* s_sense) {
    __syncthreads();
    if (threadIdx.x == 0) {
        unsigned want = *s_sense ^ 1u;
        *s_sense = want;
        __threadfence();
        if (atomicAdd(&g_bar_count, 1u) == NCTA - 1u) {
            atomicExch(&g_bar_count, 0u);
            __threadfence();
            g_bar_sense = want;
        } else {
            while (g_bar_sense != want) __nanosleep(32);
        }
        __threadfence();
    }
    __syncthreads();
}

__device__ __forceinline__ float sigf(float v) { return 1.0f / (1.0f + __expf(-v)); }
__device__ __forceinline__ float tanhfast(float v) { return 2.0f / (1.0f + __expf(-2.0f * v)) - 1.0f; }

__device__ __forceinline__ void mma16816(float* d, const unsigned* a,
                                         unsigned b0, unsigned b1) {
    asm volatile(
        "mma.sync.aligned.m16n8k16.row.col.f32.bf16.bf16.f32 "
        "{%0,%1,%2,%3}, {%4,%5,%6,%7}, {%8,%9}, {%0,%1,%2,%3};"
        : "+f"(d[0]), "+f"(d[1]), "+f"(d[2]), "+f"(d[3])
        : "r"(a[0]), "r"(a[1]), "r"(a[2]), "r"(a[3]), "r"(b0), "r"(b1));
}

__device__ __forceinline__ void ldsm4(unsigned* r, unsigned addr) {
    asm volatile("ldmatrix.sync.aligned.m8n8.x4.shared.b16 {%0,%1,%2,%3}, [%4];"
        : "=r"(r[0]), "=r"(r[1]), "=r"(r[2]), "=r"(r[3]) : "r"(addr));
}

__device__ __forceinline__ void st_bf16_cg(__nv_bfloat16* p, __nv_bfloat16 v) {
    asm volatile("st.global.cg.u16 [%0], %1;"
                 :: "l"(p), "h"(__bfloat16_as_ushort(v)) : "memory");
}

__device__ __forceinline__ void cp_async16(void* s, const void* g) {
    unsigned sa = (unsigned)__cvta_generic_to_shared(s);
    asm volatile("cp.async.cg.shared.global [%0], [%1], 16;"
                 :: "r"(sa), "l"(g) : "memory");
}
#define CP_COMMIT() asm volatile("cp.async.commit_group;" ::: "memory")
#define CP_WAIT1()  asm volatile("cp.async.wait_group 1;" ::: "memory")
#define CP_WAIT0()  asm volatile("cp.async.wait_group 0;" ::: "memory")

// ---------------------------------------------------------------------------
// Load this CTA's 16-gate-row weight slice (ih|hh fused along K) into SMEM.
__device__ void load_weights(unsigned* whi, unsigned* wlo, int WS, int xK,
                             const unsigned* ihh, const unsigned* ihl,
                             const unsigned* hhh, const unsigned* hhl,
                             int hb, int tid)
{
    const int xw = xK >> 1;
    const int twords = (xK + HH) >> 1;
    for (int idx = tid; idx < 16 * twords; idx += NTHR) {
        int c = idx / twords;
        int w = idx - c * twords;
        int j = (c & 3) * HH + hb + (c >> 2);
        unsigned vh, vl;
        if (w < xw) { vh = ihh[j * xw + w];          vl = ihl[j * xw + w]; }
        else        { vh = hhh[j * 256 + (w - xw)];  vl = hhl[j * 256 + (w - xw)]; }
        whi[c * WS + w] = vh;
        wlo[c * WS + w] = vl;
    }
    __syncthreads();
}

// Load the fused h1-part weights (16 rows x 512 K) into SMEM.
__device__ void load_wf(unsigned* whi, unsigned* wlo, int hb, int tid)
{
    const unsigned* sh = (const unsigned*)g_wf_hi;
    const unsigned* sl = (const unsigned*)g_wf_lo;
    for (int idx = tid; idx < 16 * 256; idx += NTHR) {
        int c = idx >> 8;
        int w = idx & 255;
        int j = (c & 3) * HH + hb + (c >> 2);
        whi[c * WFS + w] = sh[j * 256 + w];
        wlo[c * WFS + w] = sl[j * 256 + w];
    }
    __syncthreads();
}

// ---------------------------------------------------------------------------
// One LSTM cell slice: split-bf16 MMA, persistent SMEM weights, and
// WARP-PRIVATE 2-stage cp.async A rings -> NO CTA-wide sync in the loop.
// Warp w owns batch rows [16w, 16w+16) x all 16 gate cols.
// B weights: chunks [0,nB) from (whiA,WSA), chunks [nB,NC) from (whiB,WSB).
__device__ __noinline__ void lstm_slice(Smem* sm,
    const __nv_bfloat16* a0h, const __nv_bfloat16* a0l, int a0str, int n0,
    const __nv_bfloat16* hph, const __nv_bfloat16* hpl,
    const unsigned* whiA, const unsigned* wloA, int WSA, int nB,
    const unsigned* whiB, const unsigned* wloB, int WSB, int NC,
    const float* __restrict__ bias,
    __nv_bfloat16* hnh, __nv_bfloat16* hnl, float* hnf,
    float* c_st, int hb)
{
    const int tid  = threadIdx.x;
    const int w    = tid >> 5;
    const int lane = tid & 31;
    const int tq   = lane >> 2;   // 0..7
    const int tp   = lane & 3;    // 0..3

    unsigned* const rngH = sm->ahi[w][0];
    unsigned* const rngL = sm->alo[w][0];

    // stage chunk c of this warp's 16 rows into ring buffer `buf`
    auto stage = [&](int c, int buf) {
        const __nv_bfloat16 *sh, *sl; int k0, str;
        if (c < n0) { sh = a0h; sl = a0l; k0 = c * 64;        str = a0str; }
        else        { sh = hph; sl = hpl; k0 = (c - n0) * 64; str = HH;   }
        unsigned* dh = rngH + buf * WBUF;
        unsigned* dl = rngL + buf * WBUF;
#pragma unroll
        for (int i = 0; i < 4; ++i) {
            int o   = lane + i * 32;       // 0..127
            int row = o >> 3, seg = o & 7; // local row 0..15, 16B segment 0..7
            size_t ge = (size_t)(w * 16 + row) * str + k0 + seg * 8;
            int sw = row * AST + seg * 4;
            cp_async16(dh + sw, sh + ge);
            cp_async16(dl + sw, sl + ge);
        }
        CP_COMMIT();
    };

    float d0[4] = {0.f, 0.f, 0.f, 0.f};
    float d1[4] = {0.f, 0.f, 0.f, 0.f};

    // ldmatrix lane addressing within this warp's buffer (local rows 0..15)
    const int arow  = (lane & 7) + ((lane >> 3) & 1) * 8;
    const unsigned abyte = (unsigned)(arow * AST + ((lane >> 4) & 1) * 4) * 4u;
    const unsigned aHbase = (unsigned)__cvta_generic_to_shared(rngH) + abyte;
    const unsigned aLbase = (unsigned)__cvta_generic_to_shared(rngL) + abyte;
    const int brow  = (lane & 7) + ((lane >> 4) & 1) * 8;
    const unsigned bAoff = (unsigned)(brow * WSA + ((lane >> 3) & 1) * 4) * 4u;
    const unsigned bBoff = (unsigned)(brow * WSB + ((lane >> 3) & 1) * 4) * 4u;
    const unsigned bAH = (unsigned)__cvta_generic_to_shared(whiA) + bAoff;
    const unsigned bAL = (unsigned)__cvta_generic_to_shared(wloA) + bAoff;
    const unsigned bBH = (unsigned)__cvta_generic_to_shared(whiB) + bBoff;
    const unsigned bBL = (unsigned)__cvta_generic_to_shared(wloB) + bBoff;

    stage(0, 0);

#pragma unroll 1
    for (int c = 0; c < NC; ++c) {
        if (c + 1 < NC) { stage(c + 1, (c + 1) & 1); CP_WAIT1(); }
        else            { CP_WAIT0(); }
        __syncwarp();                    // cross-lane visibility of cp.async data

        const unsigned aH = aHbase + (unsigned)((c & 1) * (WBUF * 4));
        const unsigned aL = aLbase + (unsigned)((c & 1) * (WBUF * 4));
        unsigned bH, bL;
        if (c < nB) { bH = bAH + (unsigned)(c * 128);        bL = bAL + (unsigned)(c * 128); }
        else        { bH = bBH + (unsigned)((c - nB) * 128); bL = bBL + (unsigned)((c - nB) * 128); }

#pragma unroll
        for (int s = 0; s < 4; ++s) {
            unsigned ah[4], al[4], bh[4], bl[4];
            ldsm4(ah, aH + s * 32);
            ldsm4(al, aL + s * 32);
            ldsm4(bh, bH + s * 32);
            ldsm4(bl, bL + s * 32);
            mma16816(d0, ah, bh[0], bh[1]);
            mma16816(d0, ah, bl[0], bl[1]);
            mma16816(d0, al, bh[0], bh[1]);
            mma16816(d1, ah, bh[2], bh[3]);
            mma16816(d1, ah, bl[2], bl[3]);
            mma16816(d1, al, bh[2], bh[3]);
        }
    }

    // Epilogue: bias + i/f <-> g/o exchange (lane t <-> t^1) + cell update.
#pragma unroll
    for (int nh = 0; nh < 2; ++nh) {
        float* d = nh ? d1 : d0;
        int cA = nh * 8 + 2 * tp;
        int cB = cA + 1;
        int jA = (cA & 3) * HH + hb + (cA >> 2);
        int jB = (cB & 3) * HH + hb + (cB >> 2);
        float bA = bias[jA];
        float bB = bias[jB];
        float v0 = d[0] + bA, v1 = d[1] + bB;
        float v2 = d[2] + bA, v3 = d[3] + bB;
        float p0 = __shfl_xor_sync(0xffffffffu, v0, 1);
        float p1 = __shfl_xor_sync(0xffffffffu, v1, 1);
        float p2 = __shfl_xor_sync(0xffffffffu, v2, 1);
        float p3 = __shfl_xor_sync(0xffffffffu, v3, 1);
        if ((tp & 1) == 0) {       // even tp holds (i,f); partner holds (g,o)
            int u  = cA >> 2;
            int m0 = w * 16 + tq;
#pragma unroll
            for (int rr = 0; rr < 2; ++rr) {
                float iv = sigf(rr ? v2 : v0);
                float fv = sigf(rr ? v3 : v1);
                float gv = tanhfast(rr ? p2 : p0);
                float ov = sigf(rr ? p3 : p1);
                int gidx = (m0 + rr * 8) * HH + hb + u;
                float cv = fv * c_st[gidx] + iv * gv;
                c_st[gidx] = cv;
                float hv = ov * tanhfast(cv);
                __nv_bfloat16 hbf = __float2bfloat16(hv);
                st_bf16_cg(&hnh[gidx], hbf);
                st_bf16_cg(&hnl[gidx], __float2bfloat16(hv - __bfloat162float(hbf)));
                if (hnf) __stcg(&hnf[gidx], hv);
            }
        }
    }
}

// ---------------------------------------------------------------------------
// Projection (output only): CTA b computes out[b, s, :] = h1[b,:] @ W.T + bias.
__device__ __forceinline__ void proj_slice(
    const float* __restrict__ W, const float* __restrict__ bias,
    const float* __restrict__ h1, float* __restrict__ out_step)
{
    const int bI = blockIdx.x;
    const float* hrow = h1 + (size_t)bI * HH;
    const int w = threadIdx.x >> 5;
    const int l = threadIdx.x & 31;

#pragma unroll
    for (int p = 0; p < 8; ++p) {
        int dcol = p * 8 + w;
        const float* wr = W + (size_t)dcol * HH;
        float s = 0.0f;
#pragma unroll
        for (int m = 0; m < 4; ++m) {
            int k = m * 128 + 4 * l;
            float4 wv = *(const float4*)(wr + k);
            float4 hv = __ldcg((const float4*)(hrow + k));
            s = fmaf(wv.x, hv.x, s);
            s = fmaf(wv.y, hv.y, s);
            s = fmaf(wv.z, hv.z, s);
            s = fmaf(wv.w, hv.w, s);
        }
#pragma unroll
        for (int o = 16; o; o >>= 1) s += __shfl_xor_sync(0xffffffffu, s, o);
        if (l == 0)
            out_step[(size_t)bI * (PRD * DD) + dcol] = s + bias[dcol];
    }
}

// ---------------------------------------------------------------------------
__global__ void __launch_bounds__(NTHR, 1)
lstm_persistent(const float* projW, const float* projB, float* __restrict__ out)
{
    extern __shared__ char smem_raw[];
    Smem* sm = (Smem*)smem_raw;
    __shared__ unsigned s_sense;
    const int tid = threadIdx.x;
    const int hb  = blockIdx.x * 4;

    if (tid == 0) s_sense = g_bar_sense;

    const unsigned short z = 0;
    for (int i = blockIdx.x * NTHR + tid; i < BB * HH; i += NCTA * NTHR) {
        g_hh[0][0][i] = __ushort_as_bfloat16(z);
        g_hh[1][0][i] = __ushort_as_bfloat16(z);
        g_hl[0][0][i] = __ushort_as_bfloat16(z);
        g_hl[1][0][i] = __ushort_as_bfloat16(z);
        g_c[0][i] = 0.0f; g_c[1][i] = 0.0f;
    }
    grid_sync(&s_sense);

    int p0 = 0, p1 = 0;

    // ---- Teacher-forced region (pipelined: layer0(t) || layer1(t-1)) ----
    for (int t = 0; t <= TTF; ++t) {
        if (t == 0) {
            load_weights(sm->w0hi, sm->w0lo, W0S, DD,
                (const unsigned*)(g_whi + O_EW0I), (const unsigned*)(g_wlo + O_EW0I),
                (const unsigned*)(g_whi + O_EW0H), (const unsigned*)(g_wlo + O_EW0H), hb, tid);
            load_weights(sm->w1hi, sm->w1lo, W1S, HH,
                (const unsigned*)(g_whi + O_EW1I), (const unsigned*)(g_wlo + O_EW1I),
                (const unsigned*)(g_whi + O_EW1H), (const unsigned*)(g_wlo + O_EW1H), hb, tid);
        }
        if (t == SS)
            load_weights(sm->w0hi, sm->w0lo, W0S, DD,
                (const unsigned*)(g_whi + O_DW0I), (const unsigned*)(g_wlo + O_DW0I),
                (const unsigned*)(g_whi + O_DW0H), (const unsigned*)(g_wlo + O_DW0H), hb, tid);
        if (t == SS + 1)
            load_weights(sm->w1hi, sm->w1lo, W1S, HH,
                (const unsigned*)(g_whi + O_DW1I), (const unsigned*)(g_wlo + O_DW1I),
                (const unsigned*)(g_whi + O_DW1H), (const unsigned*)(g_wlo + O_DW1H), hb, tid);
        if (t == TTF)
            load_wf(sm->wfhi, sm->wflo, hb, tid);   // AR fused weights

        if (t < TTF) {
            bool enc = t < SS;
            const __nv_bfloat16* xh = enc ? g_xeh + (size_t)t * DD
                                          : g_xdh + (size_t)(t - SS) * DD;
            const __nv_bfloat16* xl = enc ? g_xel + (size_t)t * DD
                                          : g_xdl + (size_t)(t - SS) * DD;
            int xs = enc ? SS * DD : DECL * DD;
            lstm_slice(sm, xh, xl, xs, 1,
                       g_hh[0][p0], g_hl[0][p0],
                       sm->w0hi, sm->w0lo, W0S, NC0,
                       sm->w0hi, sm->w0lo, W0S, NC0,
                       g_bias[enc ? 0 : 2],
                       g_hh[0][p0 ^ 1], g_hl[0][p0 ^ 1], nullptr,
                       g_c[0], hb);
        }
        if (t >= 1) {
            bool enc = (t - 1) < SS;
            lstm_slice(sm, g_hh[0][p0], g_hl[0][p0], HH, 8,
                       g_hh[1][p1], g_hl[1][p1],
                       sm->w1hi, sm->w1lo, W1S, NC1,
                       sm->w1hi, sm->w1lo, W1S, NC1,
                       g_bias[enc ? 1 : 3],
                       g_hh[1][p1 ^ 1], g_hl[1][p1 ^ 1], g_h1f,
                       g_c[1], hb);
        }
        grid_sync(&s_sense);
        if (t < TTF) p0 ^= 1;
        if (t >= 1)  p1 ^= 1;
    }

    // ---- Autoregressive region (proj fused into layer0 weights) ----
    // Step s: phase A = fused-l0 (A = h1 then h0) + out[s-1]; phase B = l1.
    for (int s = 1; s < PRD; ++s) {
        lstm_slice(sm, g_hh[1][p1], g_hl[1][p1], HH, 8,
                   g_hh[0][p0], g_hl[0][p0],
                   sm->wfhi, sm->wflo, WFS, 8,
                   sm->w0hi + 32, sm->w0lo + 32, W0S, NCF,
                   g_bias[4],
                   g_hh[0][p0 ^ 1], g_hl[0][p0 ^ 1], nullptr,
                   g_c[0], hb);
        proj_slice(projW, projB, g_h1f, out + (size_t)(s - 1) * DD);
        grid_sync(&s_sense);
        p0 ^= 1;

        lstm_slice(sm, g_hh[0][p0], g_hl[0][p0], HH, 8,
                   g_hh[1][p1], g_hl[1][p1],
                   sm->w1hi, sm->w1lo, W1S, NC1,
                   sm->w1hi, sm->w1lo, W1S, NC1,
                   g_bias[3],
                   g_hh[1][p1 ^ 1], g_hl[1][p1 ^ 1], g_h1f,
                   g_c[1], hb);
        grid_sync(&s_sense);
        p1 ^= 1;
    }

    // final output slice from h1(PRD-1)
    proj_slice(projW, projB, g_h1f, out + (size_t)(PRD - 1) * DD);
}

// ---------------------------------------------------------------------------
extern "C" void kernel_launch(void* const* d_in, const int* in_sizes, int n_in,
                              void* d_out, int out_size)
{
    const float* x_enc = (const float*)d_in[0];
    const float* x_dec = (const float*)d_in[2];
    const float* eWih0 = (const float*)d_in[4];
    const float* eWhh0 = (const float*)d_in[5];
    const float* ebih0 = (const float*)d_in[6];
    const float* ebhh0 = (const float*)d_in[7];
    const float* eWih1 = (const float*)d_in[8];
    const float* eWhh1 = (const float*)d_in[9];
    const float* ebih1 = (const float*)d_in[10];
    const float* ebhh1 = (const float*)d_in[11];
    const float* dWih0 = (const float*)d_in[12];
    const float* dWhh0 = (const float*)d_in[13];
    const float* dbih0 = (const float*)d_in[14];
    const float* dbhh0 = (const float*)d_in[15];
    const float* dWih1 = (const float*)d_in[16];
    const float* dWhh1 = (const float*)d_in[17];
    const float* dbih1 = (const float*)d_in[18];
    const float* dbhh1 = (const float*)d_in[19];
    const float* projW = (const float*)d_in[20];
    const float* projB = (const float*)d_in[21];
    float* out = (float*)d_out;

    static int smem_set = 0;
    if (!smem_set) {
        cudaFuncSetAttribute(lstm_persistent,
                             cudaFuncAttributeMaxDynamicSharedMemorySize,
                             (int)sizeof(Smem));
        smem_set = 1;
    }

    prep_split<<<dim3(512, 10), 256>>>(eWih0, eWhh0, eWih1, eWhh1,
                                       dWih0, dWhh0, dWih1, dWhh1,
                                       x_enc, x_dec);
    prep_fuse<<<dim3(2048, 2), 256>>>(dWih0, projW);
    prep_bias<<<8, 256>>>(ebih0, ebhh0, ebih1, ebhh1,
                          dbih0, dbhh0, dbih1, dbhh1, dWih0, projB);

    lstm_persistent<<<NCTA, NTHR, sizeof(Smem)>>>(projW, projB, out);
}